// round 15
// baseline (speedup 1.0000x reference)
#include <cuda_runtime.h>
#include <cuda_fp16.h>
#include <mma.h>

#define NNODES 100000
#define NP 100224               // padded node count (multiple of 64)
#define NEDGES 1600000
#define F0 128
#define F1 64
#define F2 16
#define NB1 ((NNODES + 255) / 256)   // 391 scan blocks

// Scratch (device globals: allocation-free, graph-safe; zero at module load)
__device__ float  g_dinv[NNODES];
__device__ float  g_traw[NP * F1];       // gemm1 raw fp32 out (x@W1, unscaled)
__device__ __half g_h1h [NNODES * F1];   // h~ = (x@W1)*dinv[row], fp16
__device__ __half g_tsc [NNODES * F1];   // dinv*leaky(...) — layer-2 source, fp16
// dst-CSR scratch
__device__ int    g_hist  [NNODES];      // in-degree (dst); reset by agg2
__device__ int    g_rowptr[NNODES];
__device__ int    g_cursor[NNODES];
__device__ int    g_total;               // atomic range-claim counter; reset by agg2
__device__ int    g_csr   [NEDGES];      // src ids grouped by dst

// ---------------------------------------------------------------------------
// In-degree histogram over dst (8 edges/thread, 2x int4)
// g_hist enters zeroed (module load / reset by previous replay's agg2).
// ---------------------------------------------------------------------------
__global__ void gcn_hist_kernel(const int* __restrict__ dst) {
    int e8 = blockIdx.x * blockDim.x + threadIdx.x;
    if (e8 < NEDGES / 8) {
        int4 a = *(const int4*)&dst[e8 * 8];
        int4 b = *(const int4*)&dst[e8 * 8 + 4];
        atomicAdd(&g_hist[a.x], 1);
        atomicAdd(&g_hist[a.y], 1);
        atomicAdd(&g_hist[a.z], 1);
        atomicAdd(&g_hist[a.w], 1);
        atomicAdd(&g_hist[b.x], 1);
        atomicAdd(&g_hist[b.y], 1);
        atomicAdd(&g_hist[b.z], 1);
        atomicAdd(&g_hist[b.w], 1);
    }
}

// ---------------------------------------------------------------------------
// scanclaim: per-block exclusive scan + UNORDERED atomic range claim.
// CSR ranges need only be disjoint and sized hist[v]; block order is
// irrelevant to the aggregation. Also computes dinv.
// ---------------------------------------------------------------------------
__global__ void gcn_scanclaim_kernel() {
    __shared__ int s[256];
    __shared__ int base;
    int tid = threadIdx.x;
    int i = blockIdx.x * 256 + tid;
    int v = (i < NNODES) ? g_hist[i] : 0;
    s[tid] = v;
    __syncthreads();
#pragma unroll
    for (int o = 1; o < 256; o <<= 1) {
        int t = (tid >= o) ? s[tid - o] : 0;
        __syncthreads();
        s[tid] += t;
        __syncthreads();
    }
    if (tid == 255) base = atomicAdd(&g_total, s[255]);
    __syncthreads();
    if (i < NNODES) {
        int p = base + s[tid] - v;   // exclusive within claimed range
        g_rowptr[i] = p;
        g_cursor[i] = p;
        g_dinv[i] = rsqrtf(1.0f + (float)v);
    }
}

// ---------------------------------------------------------------------------
// Permute: group src ids by dst (CSR fill), int4 = 4 edges/thread
// ---------------------------------------------------------------------------
__global__ void gcn_permute_kernel(const int* __restrict__ src,
                                   const int* __restrict__ dst) {
    int e4 = blockIdx.x * blockDim.x + threadIdx.x;
    if (e4 < NEDGES / 4) {
        int4 sv = *(const int4*)&src[e4 * 4];
        int4 dv = *(const int4*)&dst[e4 * 4];
        g_csr[atomicAdd(&g_cursor[dv.x], 1)] = sv.x;
        g_csr[atomicAdd(&g_cursor[dv.y], 1)] = sv.y;
        g_csr[atomicAdd(&g_cursor[dv.z], 1)] = sv.z;
        g_csr[atomicAdd(&g_cursor[dv.w], 1)] = sv.w;
    }
}

// ---------------------------------------------------------------------------
// GEMM1 via wmma (HMMA mma.sync — baseline PTX, works on compute_103):
//    g_traw[v,:] = x[v,:] @ W1   (fp16 in, fp32 accumulate, UNSCALED)
// NO dependencies -> starts at t=0, overlaps the whole CSR-build chain.
// 64-row tiles: smem 35.8KB -> high occupancy. 256 threads = 8 warps.
// ---------------------------------------------------------------------------
#define BM1 64
#define A_LD 136               // halfs per A row (pad vs bank conflicts)
#define B_LD 72                // halfs per B row
extern __shared__ __half s_wm[];

__global__ void gcn_gemm1_wmma(const float* __restrict__ x,
                               const float* __restrict__ W1) {
    using namespace nvcuda::wmma;
    __half* As = s_wm;                      // 64 * 136 halfs  = 17408 B
    __half* Bs = s_wm + BM1 * A_LD;         // 128 * 72 halfs  = 18432 B
    int tid = threadIdx.x, wid = tid >> 5;
    int row0 = blockIdx.x * BM1;

    for (int i = tid; i < BM1 * 32; i += 256) {
        int r = i >> 5, q = i & 31;
        int v = row0 + r;
        float4 xv = (v < NNODES) ? *(const float4*)&x[v * F0 + q * 4]
                                 : make_float4(0.f, 0.f, 0.f, 0.f);
        *(__half2*)&As[r * A_LD + q * 4]     = __floats2half2_rn(xv.x, xv.y);
        *(__half2*)&As[r * A_LD + q * 4 + 2] = __floats2half2_rn(xv.z, xv.w);
    }
    for (int i = tid; i < 128 * 32; i += 256) {
        int k = i >> 5, n = (i & 31) * 2;
        float2 w = *(const float2*)&W1[k * F1 + n];
        *(__half2*)&Bs[k * B_LD + n] = __floats2half2_rn(w.x, w.y);
    }
    __syncthreads();

    int rt = wid >> 1;          // row tile 0..3 (16 rows each)
    int ch = wid & 1;           // column half 0..1 (32 cols each)

    fragment<accumulator, 16, 16, 16, float> acc[2];
#pragma unroll
    for (int c = 0; c < 2; c++) fill_fragment(acc[c], 0.0f);

    fragment<matrix_a, 16, 16, 16, __half, row_major> af;
    fragment<matrix_b, 16, 16, 16, __half, row_major> bf;
#pragma unroll
    for (int k = 0; k < 8; k++) {
        load_matrix_sync(af, As + rt * 16 * A_LD + k * 16, A_LD);
#pragma unroll
        for (int c = 0; c < 2; c++) {
            load_matrix_sync(bf, Bs + k * 16 * B_LD + ch * 32 + c * 16, B_LD);
            mma_sync(acc[c], af, bf, acc[c]);
        }
    }

#pragma unroll
    for (int c = 0; c < 2; c++)
        store_matrix_sync(&g_traw[(row0 + rt * 16) * F1 + ch * 32 + c * 16],
                          acc[c], F1, mem_row_major);
}

// ---------------------------------------------------------------------------
// scale_h1: g_h1h[v,:] = fp16( g_traw[v,:] * dinv[v] )
// ---------------------------------------------------------------------------
__global__ void gcn_scale_h1_kernel() {
    int t = blockIdx.x * blockDim.x + threadIdx.x;
    if (t >= NNODES * 32) return;
    int v = t >> 5, j = (t & 31) * 2;
    float dv = g_dinv[v];
    float2 u = *(const float2*)&g_traw[v * F1 + j];
    *(__half2*)&g_h1h[v * F1 + j] = __floats2half2_rn(u.x * dv, u.y * dv);
}

// ---------------------------------------------------------------------------
// Layer-1 aggregation + activation (warp per node, independent warps):
//   t = leaky_relu(dinv_v*(h1[v] + sum_s h1[s]) + b1)
//   g_tsc[v,:] = fp16( dinv_v * t )          -- layer-2 source, pre-scaled
// ---------------------------------------------------------------------------
__global__ void gcn_agg1_kernel(const float* __restrict__ b1) {
    int w = (blockIdx.x * blockDim.x + threadIdx.x) >> 5;
    int lane = threadIdx.x & 31;
    int v = w;                       // grid sized exactly: no overflow
    int beg = g_rowptr[v];
    int len = g_hist[v];

    float2 acc = __half22float2(*(const __half2*)&g_h1h[v * F1 + lane * 2]);

    const int* __restrict__ idx = &g_csr[beg];
    int i = 0;
    for (; i + 4 <= len; i += 4) {
        int s0 = idx[i], s1 = idx[i + 1], s2 = idx[i + 2], s3 = idx[i + 3];
        float2 u0 = __half22float2(*(const __half2*)&g_h1h[s0 * F1 + lane * 2]);
        float2 u1 = __half22float2(*(const __half2*)&g_h1h[s1 * F1 + lane * 2]);
        float2 u2 = __half22float2(*(const __half2*)&g_h1h[s2 * F1 + lane * 2]);
        float2 u3 = __half22float2(*(const __half2*)&g_h1h[s3 * F1 + lane * 2]);
        acc.x += u0.x + u1.x + u2.x + u3.x;
        acc.y += u0.y + u1.y + u2.y + u3.y;
    }
    for (; i < len; i++) {
        int s = idx[i];
        float2 u = __half22float2(*(const __half2*)&g_h1h[s * F1 + lane * 2]);
        acc.x += u.x; acc.y += u.y;
    }

    float dv = g_dinv[v];
    float t0 = dv * acc.x + b1[lane * 2];
    float t1 = dv * acc.y + b1[lane * 2 + 1];
    t0 = t0 >= 0.f ? t0 : 0.2f * t0;
    t1 = t1 >= 0.f ? t1 : 0.2f * t1;
    *(__half2*)&g_tsc[v * F1 + lane * 2] = __floats2half2_rn(t0 * dv, t1 * dv);
}

// ---------------------------------------------------------------------------
// Layer-2 FUSED aggregation + W2 + bias + log_softmax (warp per node).
// W2 factored out of the segment sum:
//   out[v] = logsoftmax( dinv_v * ( sum_{s in N(v)+self} tsc[s] ) @ W2 + b2 )
// Per-warp W2 apply via smem (no cross-warp sync after the initial W2 load).
// Also resets g_hist / g_total for the next graph replay.
// ---------------------------------------------------------------------------
__global__ void gcn_agg2_kernel(const float* __restrict__ W2,
                                const float* __restrict__ b2,
                                float* __restrict__ out) {
    __shared__ __align__(16) float W2s[F1 * F2];   // 4 KB
    __shared__ __align__(16) float ab[8][F1];      // 2 KB (8 warps x 64)
    int tid = threadIdx.x, wid = tid >> 5, lane = tid & 31;
    for (int i = tid; i < F1 * F2; i += 256) W2s[i] = W2[i];
    __syncthreads();                 // only block-wide sync (cheap, uniform)

    int v = blockIdx.x * 8 + wid;    // grid sized exactly: 12500*8 = NNODES
    int beg = g_rowptr[v];
    int len = g_hist[v];

    float2 acc = __half22float2(*(const __half2*)&g_tsc[v * F1 + lane * 2]);

    const int* __restrict__ idx = &g_csr[beg];
    int i = 0;
    for (; i + 4 <= len; i += 4) {
        int s0 = idx[i], s1 = idx[i + 1], s2 = idx[i + 2], s3 = idx[i + 3];
        float2 u0 = __half22float2(*(const __half2*)&g_tsc[s0 * F1 + lane * 2]);
        float2 u1 = __half22float2(*(const __half2*)&g_tsc[s1 * F1 + lane * 2]);
        float2 u2 = __half22float2(*(const __half2*)&g_tsc[s2 * F1 + lane * 2]);
        float2 u3 = __half22float2(*(const __half2*)&g_tsc[s3 * F1 + lane * 2]);
        acc.x += u0.x + u1.x + u2.x + u3.x;
        acc.y += u0.y + u1.y + u2.y + u3.y;
    }
    for (; i < len; i++) {
        int s = idx[i];
        float2 u = __half22float2(*(const __half2*)&g_tsc[s * F1 + lane * 2]);
        acc.x += u.x; acc.y += u.y;
    }

    // Park aggregate in smem; per-warp W2 apply (lanes 0-15: j 0..31,
    // lanes 16-31: j 32..63; fold with one shfl).
    *(float2*)&ab[wid][lane * 2] = acc;
    __syncwarp();

    int m = lane & 15;
    int jb = (lane >> 4) * 32;
    float h = 0.f;
#pragma unroll
    for (int j = 0; j < 32; j++)
        h = fmaf(ab[wid][jb + j], W2s[(jb + j) * F2 + m], h);
    h += __shfl_down_sync(0xffffffffu, h, 16);

    float dv = g_dinv[v];
    float t = dv * h + b2[m];

    // log_softmax over 16 features (xor shuffles stay within half-warp)
    float mx = t;
#pragma unroll
    for (int o = 8; o >= 1; o >>= 1)
        mx = fmaxf(mx, __shfl_xor_sync(0xffffffffu, mx, o));
    float ex = expf(t - mx);
    float sum = ex;
#pragma unroll
    for (int o = 8; o >= 1; o >>= 1)
        sum += __shfl_xor_sync(0xffffffffu, sum, o);
    float lse = mx + logf(sum);

    if (lane < 16) out[v * F2 + m] = t - lse;

    // reset CSR state for the next graph replay (deterministic re-entry)
    if (lane == 0) {
        g_hist[v] = 0;
        if (v == 0) g_total = 0;
    }
}

// ---------------------------------------------------------------------------
// Launch: fork-join graph (7 nodes).
//   sA: gemm1_wmma (t=0, NO deps) -> (wait evD) scale_h1 -> evS
//   s0: hist -> scanclaim(evD) -> permute -> (wait evS) agg1 -> agg2
// ---------------------------------------------------------------------------
extern "C" void kernel_launch(void* const* d_in, const int* in_sizes, int n_in,
                              void* d_out, int out_size) {
    const float* x  = (const float*)d_in[0];
    const int*   ei = (const int*)  d_in[1];
    const float* W1 = (const float*)d_in[2];
    const float* b1 = (const float*)d_in[3];
    const float* W2 = (const float*)d_in[4];
    const float* b2 = (const float*)d_in[5];
    float* out = (float*)d_out;

    const int* src = ei;
    const int* dst = ei + NEDGES;

    const int g1_smem = (BM1 * A_LD + 128 * B_LD) * (int)sizeof(__half); // 35.8KB
    cudaFuncSetAttribute(gcn_gemm1_wmma,
                         cudaFuncAttributeMaxDynamicSharedMemorySize, g1_smem);

    cudaStream_t sA;
    cudaStreamCreateWithFlags(&sA, cudaStreamNonBlocking);
    cudaEvent_t ev0, evD, evS;
    cudaEventCreateWithFlags(&ev0, cudaEventDisableTiming);
    cudaEventCreateWithFlags(&evD, cudaEventDisableTiming);
    cudaEventCreateWithFlags(&evS, cudaEventDisableTiming);

    // fork: side stream joins capture via origin-stream event
    cudaEventRecord(ev0, 0);
    cudaStreamWaitEvent(sA, ev0, 0);

    gcn_gemm1_wmma<<<NP / BM1, 256, g1_smem, sA>>>(x, W1);   // t=0, no deps

    gcn_hist_kernel     <<<(NEDGES / 8 + 255) / 256, 256>>>(dst);   // s0
    gcn_scanclaim_kernel<<<NB1, 256>>>();
    cudaEventRecord(evD, 0);

    cudaStreamWaitEvent(sA, evD, 0);                         // scale needs dinv
    gcn_scale_h1_kernel<<<(NNODES * 32 + 255) / 256, 256, 0, sA>>>();
    cudaEventRecord(evS, sA);

    gcn_permute_kernel<<<(NEDGES / 4 + 255) / 256, 256>>>(src, dst);  // overlaps

    cudaStreamWaitEvent(0, evS, 0);                          // join
    gcn_agg1_kernel<<<NNODES * 32 / 256, 256>>>(b1);
    gcn_agg2_kernel<<<NNODES / 8, 256>>>(W2, b2, out);
}

// round 16
// speedup vs baseline: 1.0686x; 1.0686x over previous
#include <cuda_runtime.h>
#include <cuda_fp16.h>
#include <mma.h>

#define NNODES 100000
#define NP 100224               // padded node count (multiple of 64)
#define NEDGES 1600000
#define F0 128
#define F1 64
#define F2 16
#define NB1 ((NNODES + 255) / 256)   // 391 scan blocks

// Scratch (device globals: allocation-free, graph-safe; zero at module load)
__device__ float  g_dinv [NNODES];
__device__ __half g_h1raw[NP * F1];      // gemm1 fp16 out (x@W1, unscaled)
__device__ __half g_h1h  [NNODES * F1];  // h~ = (x@W1)*dinv[row], fp16
__device__ float  g_t    [NNODES * F1];  // activated layer-1 output
__device__ float  g_h2   [NNODES * F2];  // h~2 = (t@W2)*dinv[row]
// dst-CSR scratch
__device__ int    g_hist  [NNODES];      // in-degree (dst); reset by agg2
__device__ int    g_rowptr[NNODES];
__device__ int    g_cursor[NNODES];
__device__ int    g_total;               // atomic claim counter; reset by agg2
__device__ int    g_csr   [NEDGES];      // src ids grouped by dst

// ---------------------------------------------------------------------------
// In-degree histogram over dst (8 edges/thread, 2x int4).
// g_hist enters zeroed (module load / reset by previous replay's agg2).
// ---------------------------------------------------------------------------
__global__ void gcn_hist_kernel(const int* __restrict__ dst) {
    int e8 = blockIdx.x * blockDim.x + threadIdx.x;
    if (e8 < NEDGES / 8) {
        int4 a = *(const int4*)&dst[e8 * 8];
        int4 b = *(const int4*)&dst[e8 * 8 + 4];
        atomicAdd(&g_hist[a.x], 1);
        atomicAdd(&g_hist[a.y], 1);
        atomicAdd(&g_hist[a.z], 1);
        atomicAdd(&g_hist[a.w], 1);
        atomicAdd(&g_hist[b.x], 1);
        atomicAdd(&g_hist[b.y], 1);
        atomicAdd(&g_hist[b.z], 1);
        atomicAdd(&g_hist[b.w], 1);
    }
}

// ---------------------------------------------------------------------------
// scanclaim: per-block exclusive scan + UNORDERED atomic range claim.
// CSR ranges need only be disjoint and sized hist[v]; block order is
// irrelevant to the aggregation. Also computes dinv.
// ---------------------------------------------------------------------------
__global__ void gcn_scanclaim_kernel() {
    __shared__ int s[256];
    __shared__ int base;
    int tid = threadIdx.x;
    int i = blockIdx.x * 256 + tid;
    int v = (i < NNODES) ? g_hist[i] : 0;
    s[tid] = v;
    __syncthreads();
#pragma unroll
    for (int o = 1; o < 256; o <<= 1) {
        int t = (tid >= o) ? s[tid - o] : 0;
        __syncthreads();
        s[tid] += t;
        __syncthreads();
    }
    if (tid == 255) base = atomicAdd(&g_total, s[255]);
    __syncthreads();
    if (i < NNODES) {
        int p = base + s[tid] - v;   // exclusive within claimed range
        g_rowptr[i] = p;
        g_cursor[i] = p;
        g_dinv[i] = rsqrtf(1.0f + (float)v);
    }
}

// ---------------------------------------------------------------------------
// Permute: group src ids by dst (CSR fill), int4 = 4 edges/thread
// ---------------------------------------------------------------------------
__global__ void gcn_permute_kernel(const int* __restrict__ src,
                                   const int* __restrict__ dst) {
    int e4 = blockIdx.x * blockDim.x + threadIdx.x;
    if (e4 < NEDGES / 4) {
        int4 sv = *(const int4*)&src[e4 * 4];
        int4 dv = *(const int4*)&dst[e4 * 4];
        g_csr[atomicAdd(&g_cursor[dv.x], 1)] = sv.x;
        g_csr[atomicAdd(&g_cursor[dv.y], 1)] = sv.y;
        g_csr[atomicAdd(&g_cursor[dv.z], 1)] = sv.z;
        g_csr[atomicAdd(&g_cursor[dv.w], 1)] = sv.w;
    }
}

// ---------------------------------------------------------------------------
// GEMM1 via wmma (HMMA mma.sync — baseline PTX, works on compute_103):
//    g_h1raw[v,:] = fp16( x[v,:] @ W1 )   (UNSCALED; dinv applied by scale_h1)
// NO dependencies -> starts at t=0, overlaps the whole CSR-build chain.
// 64-row tiles, 256 threads = 8 warps; epilogue stages fp32 in smem then
// converts to fp16, coalesced.
// ---------------------------------------------------------------------------
#define BM1 64
#define A_LD 136               // halfs per A row (pad vs bank conflicts)
#define B_LD 72                // halfs per B row
#define D_LD 68                // floats per epilogue staging row
extern __shared__ __half s_wm[];

__global__ void gcn_gemm1_wmma(const float* __restrict__ x,
                               const float* __restrict__ W1) {
    using namespace nvcuda::wmma;
    __half* As = s_wm;                      // 64 * 136 halfs  = 17408 B
    __half* Bs = s_wm + BM1 * A_LD;         // 128 * 72 halfs  = 18432 B
    int tid = threadIdx.x, wid = tid >> 5;
    int row0 = blockIdx.x * BM1;

    for (int i = tid; i < BM1 * 32; i += 256) {
        int r = i >> 5, q = i & 31;
        int v = row0 + r;
        float4 xv = (v < NNODES) ? *(const float4*)&x[v * F0 + q * 4]
                                 : make_float4(0.f, 0.f, 0.f, 0.f);
        *(__half2*)&As[r * A_LD + q * 4]     = __floats2half2_rn(xv.x, xv.y);
        *(__half2*)&As[r * A_LD + q * 4 + 2] = __floats2half2_rn(xv.z, xv.w);
    }
    for (int i = tid; i < 128 * 32; i += 256) {
        int k = i >> 5, n = (i & 31) * 2;
        float2 w = *(const float2*)&W1[k * F1 + n];
        *(__half2*)&Bs[k * B_LD + n] = __floats2half2_rn(w.x, w.y);
    }
    __syncthreads();

    int rt = wid >> 1;          // row tile 0..3 (16 rows each)
    int ch = wid & 1;           // column half 0..1 (32 cols each)

    fragment<accumulator, 16, 16, 16, float> acc[2];
#pragma unroll
    for (int c = 0; c < 2; c++) fill_fragment(acc[c], 0.0f);

    fragment<matrix_a, 16, 16, 16, __half, row_major> af;
    fragment<matrix_b, 16, 16, 16, __half, row_major> bf;
#pragma unroll
    for (int k = 0; k < 8; k++) {
        load_matrix_sync(af, As + rt * 16 * A_LD + k * 16, A_LD);
#pragma unroll
        for (int c = 0; c < 2; c++) {
            load_matrix_sync(bf, Bs + k * 16 * B_LD + ch * 32 + c * 16, B_LD);
            mma_sync(acc[c], af, bf, acc[c]);
        }
    }

    // Epilogue: stage fp32 in smem (reuses As area: 64*68*4 = 17408 B),
    // convert to fp16, store coalesced.
    __syncthreads();
    float* ds = (float*)s_wm;
#pragma unroll
    for (int c = 0; c < 2; c++)
        store_matrix_sync(&ds[(rt * 16) * D_LD + ch * 32 + c * 16], acc[c],
                          D_LD, mem_row_major);
    __syncthreads();

    for (int i = tid; i < BM1 * 32; i += 256) {
        int r = i >> 5, j = (i & 31) * 2;
        float2 u = *(const float2*)&ds[r * D_LD + j];
        *(__half2*)&g_h1raw[(row0 + r) * F1 + j] = __floats2half2_rn(u.x, u.y);
    }
}

// ---------------------------------------------------------------------------
// scale_h1: g_h1h[v,:] = fp16-in, fp16-out scale by dinv (4 halfs/thread)
// ---------------------------------------------------------------------------
__global__ void gcn_scale_h1_kernel() {
    int t = blockIdx.x * blockDim.x + threadIdx.x;
    if (t >= NNODES * 16) return;
    int v = t >> 4, j = (t & 15) * 4;
    float dv = g_dinv[v];
    __half2 a = *(const __half2*)&g_h1raw[v * F1 + j];
    __half2 b = *(const __half2*)&g_h1raw[v * F1 + j + 2];
    float2 fa = __half22float2(a), fb = __half22float2(b);
    *(__half2*)&g_h1h[v * F1 + j]     = __floats2half2_rn(fa.x * dv, fa.y * dv);
    *(__half2*)&g_h1h[v * F1 + j + 2] = __floats2half2_rn(fb.x * dv, fb.y * dv);
}

// ---------------------------------------------------------------------------
// Layer-1 aggregation + activation (warp per node, independent warps):
//    t[v] = leaky_relu(dinv[v] * (h1[v] + sum_{s->v} h1[s]) + b1)
// ---------------------------------------------------------------------------
__global__ void gcn_agg1_kernel(const float* __restrict__ b1) {
    int w = (blockIdx.x * blockDim.x + threadIdx.x) >> 5;
    int lane = threadIdx.x & 31;
    if (w >= NNODES) return;
    int v = w;
    int beg = g_rowptr[v];
    int len = g_hist[v];

    float2 acc = __half22float2(*(const __half2*)&g_h1h[v * F1 + lane * 2]);

    const int* __restrict__ idx = &g_csr[beg];
    int i = 0;
    for (; i + 4 <= len; i += 4) {
        int s0 = idx[i], s1 = idx[i + 1], s2 = idx[i + 2], s3 = idx[i + 3];
        float2 u0 = __half22float2(*(const __half2*)&g_h1h[s0 * F1 + lane * 2]);
        float2 u1 = __half22float2(*(const __half2*)&g_h1h[s1 * F1 + lane * 2]);
        float2 u2 = __half22float2(*(const __half2*)&g_h1h[s2 * F1 + lane * 2]);
        float2 u3 = __half22float2(*(const __half2*)&g_h1h[s3 * F1 + lane * 2]);
        acc.x += u0.x + u1.x + u2.x + u3.x;
        acc.y += u0.y + u1.y + u2.y + u3.y;
    }
    for (; i < len; i++) {
        int s = idx[i];
        float2 u = __half22float2(*(const __half2*)&g_h1h[s * F1 + lane * 2]);
        acc.x += u.x; acc.y += u.y;
    }

    float dv = g_dinv[v];
    float t0 = dv * acc.x + b1[lane * 2];
    float t1 = dv * acc.y + b1[lane * 2 + 1];
    t0 = t0 >= 0.f ? t0 : 0.2f * t0;
    t1 = t1 >= 0.f ? t1 : 0.2f * t1;
    *(float2*)&g_t[v * F1 + lane * 2] = make_float2(t0, t1);
}

// ---------------------------------------------------------------------------
// GEMM2: h2[v,:] = (t[v,:] @ W2) * dinv[v]    [N,64]x[64,16]
// ---------------------------------------------------------------------------
__global__ void gcn_gemm2_kernel(const float* __restrict__ W2) {
    __shared__ __align__(16) float W2s[F1 * F2];
    __shared__ __align__(16) float ts[16][F1];
    int tid = threadIdx.x;
    for (int i = tid; i < F1 * F2; i += 256) W2s[i] = W2[i];

    int v0 = blockIdx.x * 16;
    for (int i = tid; i < 16 * 16; i += 256) {
        int r = i >> 4, q = i & 15;
        *(float4*)&ts[r][q * 4] = *(const float4*)&g_t[(v0 + r) * F1 + q * 4];
    }
    __syncthreads();

    int r = tid >> 4;
    int m = tid & 15;
    int v = v0 + r;
    float acc = 0.f;
#pragma unroll
    for (int j = 0; j < F1; j++) acc += ts[r][j] * W2s[j * F2 + m];
    g_h2[v * F2 + m] = acc * g_dinv[v];
}

// ---------------------------------------------------------------------------
// Layer-2 aggregation + log_softmax (warp per node).
// Also resets g_hist / g_total for the next graph replay.
// ---------------------------------------------------------------------------
__global__ void gcn_agg2_kernel(const float* __restrict__ b2,
                                float* __restrict__ out) {
    int w = (blockIdx.x * blockDim.x + threadIdx.x) >> 5;
    int lane = threadIdx.x & 31;
    if (w >= NNODES) return;
    int v = w;
    int beg = g_rowptr[v];
    int len = g_hist[v];
    int f = lane & 15;

    float acc = 0.f;
    const int* __restrict__ idx = &g_csr[beg];
    for (int i = (lane >> 4); i < len; i += 2) {
        int s = idx[i];
        acc += g_h2[s * F2 + f];
    }
    acc += __shfl_down_sync(0xffffffffu, acc, 16);

    float dv = g_dinv[v];
    float t = dv * (acc + g_h2[v * F2 + f]) + b2[f];

    float mx = t;
#pragma unroll
    for (int o = 8; o >= 1; o >>= 1)
        mx = fmaxf(mx, __shfl_xor_sync(0xffffffffu, mx, o));
    float ex = expf(t - mx);
    float sum = ex;
#pragma unroll
    for (int o = 8; o >= 1; o >>= 1)
        sum += __shfl_xor_sync(0xffffffffu, sum, o);
    float lse = mx + logf(sum);

    if (lane < 16) out[v * F2 + f] = t - lse;

    // reset CSR state for the next graph replay (deterministic re-entry)
    if (lane == 0) {
        g_hist[v] = 0;
        if (v == 0) g_total = 0;
    }
}

// ---------------------------------------------------------------------------
// Launch: fork-join graph (8 nodes).
//   sA: gemm1_wmma (t=0, NO deps) -> (wait evD) scale_h1 -> evS
//   s0: hist -> scanclaim(evD) -> permute -> (wait evS) agg1 -> gemm2 -> agg2
// ---------------------------------------------------------------------------
extern "C" void kernel_launch(void* const* d_in, const int* in_sizes, int n_in,
                              void* d_out, int out_size) {
    const float* x  = (const float*)d_in[0];
    const int*   ei = (const int*)  d_in[1];
    const float* W1 = (const float*)d_in[2];
    const float* b1 = (const float*)d_in[3];
    const float* W2 = (const float*)d_in[4];
    const float* b2 = (const float*)d_in[5];
    float* out = (float*)d_out;

    const int* src = ei;
    const int* dst = ei + NEDGES;

    const int g1_smem = (BM1 * A_LD + 128 * B_LD) * (int)sizeof(__half); // 35.8KB
    cudaFuncSetAttribute(gcn_gemm1_wmma,
                         cudaFuncAttributeMaxDynamicSharedMemorySize, g1_smem);

    cudaStream_t sA;
    cudaStreamCreateWithFlags(&sA, cudaStreamNonBlocking);
    cudaEvent_t ev0, evD, evS;
    cudaEventCreateWithFlags(&ev0, cudaEventDisableTiming);
    cudaEventCreateWithFlags(&evD, cudaEventDisableTiming);
    cudaEventCreateWithFlags(&evS, cudaEventDisableTiming);

    // fork: side stream joins capture via origin-stream event
    cudaEventRecord(ev0, 0);
    cudaStreamWaitEvent(sA, ev0, 0);

    gcn_gemm1_wmma<<<NP / BM1, 256, g1_smem, sA>>>(x, W1);   // t=0, no deps

    gcn_hist_kernel     <<<(NEDGES / 8 + 255) / 256, 256>>>(dst);   // s0
    gcn_scanclaim_kernel<<<NB1, 256>>>();
    cudaEventRecord(evD, 0);

    cudaStreamWaitEvent(sA, evD, 0);                         // scale needs dinv
    gcn_scale_h1_kernel<<<(NNODES * 16 + 255) / 256, 256, 0, sA>>>();
    cudaEventRecord(evS, sA);

    gcn_permute_kernel<<<(NEDGES / 4 + 255) / 256, 256>>>(src, dst);  // overlaps

    cudaStreamWaitEvent(0, evS, 0);                          // join
    gcn_agg1_kernel <<<(NNODES * 32 + 255) / 256, 256>>>(b1);
    gcn_gemm2_kernel<<<NNODES / 16, 256>>>(W2);
    gcn_agg2_kernel <<<(NNODES * 32 + 255) / 256, 256>>>(b2, out);
}

// round 17
// speedup vs baseline: 1.0992x; 1.0286x over previous
#include <cuda_runtime.h>
#include <cuda_fp16.h>
#include <mma.h>

#define NNODES 100000
#define NP 100224               // padded node count (multiple of 64)
#define NEDGES 1600000
#define F0 128
#define F1 64
#define F2 16
#define NB1 ((NNODES + 255) / 256)   // 391 scan blocks

// Scratch (device globals: allocation-free, graph-safe; zero at module load)
__device__ float  g_dinv [NNODES];
__device__ __half g_h1raw[NP * F1];      // gemm1 fp16 out (x@W1, unscaled)
__device__ __half g_h1h  [NNODES * F1];  // h~ = (x@W1)*dinv[row], fp16
__device__ float  g_h2   [NNODES * F2];  // h~2 = (t@W2)*dinv[row]
// dst-CSR scratch
__device__ int    g_hist  [NNODES];      // in-degree (dst); reset by agg2
__device__ int    g_rowptr[NNODES];
__device__ int    g_cursor[NNODES];
__device__ int    g_total;               // atomic claim counter; reset by agg2
__device__ int    g_csr   [NEDGES];      // src ids grouped by dst

// ---------------------------------------------------------------------------
// In-degree histogram over dst (8 edges/thread, 2x int4).
// g_hist enters zeroed (module load / reset by previous replay's agg2).
// ---------------------------------------------------------------------------
__global__ void gcn_hist_kernel(const int* __restrict__ dst) {
    int e8 = blockIdx.x * blockDim.x + threadIdx.x;
    if (e8 < NEDGES / 8) {
        int4 a = *(const int4*)&dst[e8 * 8];
        int4 b = *(const int4*)&dst[e8 * 8 + 4];
        atomicAdd(&g_hist[a.x], 1);
        atomicAdd(&g_hist[a.y], 1);
        atomicAdd(&g_hist[a.z], 1);
        atomicAdd(&g_hist[a.w], 1);
        atomicAdd(&g_hist[b.x], 1);
        atomicAdd(&g_hist[b.y], 1);
        atomicAdd(&g_hist[b.z], 1);
        atomicAdd(&g_hist[b.w], 1);
    }
}

// ---------------------------------------------------------------------------
// scanclaim: per-block exclusive scan + UNORDERED atomic range claim.
// CSR ranges need only be disjoint and sized hist[v]; block order is
// irrelevant to the aggregation. Also computes dinv.
// ---------------------------------------------------------------------------
__global__ void gcn_scanclaim_kernel() {
    __shared__ int s[256];
    __shared__ int base;
    int tid = threadIdx.x;
    int i = blockIdx.x * 256 + tid;
    int v = (i < NNODES) ? g_hist[i] : 0;
    s[tid] = v;
    __syncthreads();
#pragma unroll
    for (int o = 1; o < 256; o <<= 1) {
        int t = (tid >= o) ? s[tid - o] : 0;
        __syncthreads();
        s[tid] += t;
        __syncthreads();
    }
    if (tid == 255) base = atomicAdd(&g_total, s[255]);
    __syncthreads();
    if (i < NNODES) {
        int p = base + s[tid] - v;   // exclusive within claimed range
        g_rowptr[i] = p;
        g_cursor[i] = p;
        g_dinv[i] = rsqrtf(1.0f + (float)v);
    }
}

// ---------------------------------------------------------------------------
// Permute: group src ids by dst (CSR fill), int4 = 4 edges/thread
// ---------------------------------------------------------------------------
__global__ void gcn_permute_kernel(const int* __restrict__ src,
                                   const int* __restrict__ dst) {
    int e4 = blockIdx.x * blockDim.x + threadIdx.x;
    if (e4 < NEDGES / 4) {
        int4 sv = *(const int4*)&src[e4 * 4];
        int4 dv = *(const int4*)&dst[e4 * 4];
        g_csr[atomicAdd(&g_cursor[dv.x], 1)] = sv.x;
        g_csr[atomicAdd(&g_cursor[dv.y], 1)] = sv.y;
        g_csr[atomicAdd(&g_cursor[dv.z], 1)] = sv.z;
        g_csr[atomicAdd(&g_cursor[dv.w], 1)] = sv.w;
    }
}

// ---------------------------------------------------------------------------
// GEMM1 via wmma (HMMA mma.sync — baseline PTX, works on compute_103):
//    g_h1raw[v,:] = fp16( x[v,:] @ W1 )   (UNSCALED; dinv applied by scale_h1)
// NO dependencies -> starts at t=0, overlaps the whole CSR-build chain.
// ---------------------------------------------------------------------------
#define BM1 64
#define A_LD 136               // halfs per A row (pad vs bank conflicts)
#define B_LD 72                // halfs per B row
#define D_LD 68                // floats per epilogue staging row
extern __shared__ __half s_wm[];

__global__ void gcn_gemm1_wmma(const float* __restrict__ x,
                               const float* __restrict__ W1) {
    using namespace nvcuda::wmma;
    __half* As = s_wm;                      // 64 * 136 halfs  = 17408 B
    __half* Bs = s_wm + BM1 * A_LD;         // 128 * 72 halfs  = 18432 B
    int tid = threadIdx.x, wid = tid >> 5;
    int row0 = blockIdx.x * BM1;

    for (int i = tid; i < BM1 * 32; i += 256) {
        int r = i >> 5, q = i & 31;
        int v = row0 + r;
        float4 xv = (v < NNODES) ? *(const float4*)&x[v * F0 + q * 4]
                                 : make_float4(0.f, 0.f, 0.f, 0.f);
        *(__half2*)&As[r * A_LD + q * 4]     = __floats2half2_rn(xv.x, xv.y);
        *(__half2*)&As[r * A_LD + q * 4 + 2] = __floats2half2_rn(xv.z, xv.w);
    }
    for (int i = tid; i < 128 * 32; i += 256) {
        int k = i >> 5, n = (i & 31) * 2;
        float2 w = *(const float2*)&W1[k * F1 + n];
        *(__half2*)&Bs[k * B_LD + n] = __floats2half2_rn(w.x, w.y);
    }
    __syncthreads();

    int rt = wid >> 1;          // row tile 0..3 (16 rows each)
    int ch = wid & 1;           // column half 0..1 (32 cols each)

    fragment<accumulator, 16, 16, 16, float> acc[2];
#pragma unroll
    for (int c = 0; c < 2; c++) fill_fragment(acc[c], 0.0f);

    fragment<matrix_a, 16, 16, 16, __half, row_major> af;
    fragment<matrix_b, 16, 16, 16, __half, row_major> bf;
#pragma unroll
    for (int k = 0; k < 8; k++) {
        load_matrix_sync(af, As + rt * 16 * A_LD + k * 16, A_LD);
#pragma unroll
        for (int c = 0; c < 2; c++) {
            load_matrix_sync(bf, Bs + k * 16 * B_LD + ch * 32 + c * 16, B_LD);
            mma_sync(acc[c], af, bf, acc[c]);
        }
    }

    // Epilogue: stage fp32 in smem, convert to fp16, store coalesced.
    __syncthreads();
    float* ds = (float*)s_wm;
#pragma unroll
    for (int c = 0; c < 2; c++)
        store_matrix_sync(&ds[(rt * 16) * D_LD + ch * 32 + c * 16], acc[c],
                          D_LD, mem_row_major);
    __syncthreads();

    for (int i = tid; i < BM1 * 32; i += 256) {
        int r = i >> 5, j = (i & 31) * 2;
        float2 u = *(const float2*)&ds[r * D_LD + j];
        *(__half2*)&g_h1raw[(row0 + r) * F1 + j] = __floats2half2_rn(u.x, u.y);
    }
}

// ---------------------------------------------------------------------------
// scale_h1: g_h1h[v,:] = fp16-in, fp16-out scale by dinv (4 halfs/thread)
// ---------------------------------------------------------------------------
__global__ void gcn_scale_h1_kernel() {
    int t = blockIdx.x * blockDim.x + threadIdx.x;
    if (t >= NNODES * 16) return;
    int v = t >> 4, j = (t & 15) * 4;
    float dv = g_dinv[v];
    __half2 a = *(const __half2*)&g_h1raw[v * F1 + j];
    __half2 b = *(const __half2*)&g_h1raw[v * F1 + j + 2];
    float2 fa = __half22float2(a), fb = __half22float2(b);
    *(__half2*)&g_h1h[v * F1 + j]     = __floats2half2_rn(fa.x * dv, fa.y * dv);
    *(__half2*)&g_h1h[v * F1 + j + 2] = __floats2half2_rn(fb.x * dv, fb.y * dv);
}

// ---------------------------------------------------------------------------
// FUSED layer-1 aggregation + activation + per-warp GEMM2:
//   warp per node (warps INDEPENDENT — only a uniform pre-gather W2 sync):
//     t = leaky_relu(dinv*(h1[v] + sum_s h1[s]) + b1)       (fp32, in regs)
//     park t in per-warp smem, __syncwarp, half-warp W2 apply,
//     h2[v,:] = (t @ W2) * dinv  written directly (g_t round-trip deleted).
// ---------------------------------------------------------------------------
__global__ void gcn_agg1_gemm2_kernel(const float* __restrict__ b1,
                                      const float* __restrict__ W2) {
    __shared__ __align__(16) float W2s[F1 * F2];   // 4 KB
    __shared__ __align__(16) float tw[8][F1];      // 2 KB, per-warp t rows
    int tid = threadIdx.x, wid = tid >> 5, lane = tid & 31;
    for (int i = tid; i < F1 * F2; i += 256) W2s[i] = W2[i];
    __syncthreads();   // uniform, pre-gather: no degree coupling

    int v = blockIdx.x * 8 + wid;    // grid exact: 12500*8 = NNODES
    int beg = g_rowptr[v];
    int len = g_hist[v];

    float2 acc = __half22float2(*(const __half2*)&g_h1h[v * F1 + lane * 2]);

    const int* __restrict__ idx = &g_csr[beg];
    int i = 0;
    for (; i + 4 <= len; i += 4) {
        int s0 = idx[i], s1 = idx[i + 1], s2 = idx[i + 2], s3 = idx[i + 3];
        float2 u0 = __half22float2(*(const __half2*)&g_h1h[s0 * F1 + lane * 2]);
        float2 u1 = __half22float2(*(const __half2*)&g_h1h[s1 * F1 + lane * 2]);
        float2 u2 = __half22float2(*(const __half2*)&g_h1h[s2 * F1 + lane * 2]);
        float2 u3 = __half22float2(*(const __half2*)&g_h1h[s3 * F1 + lane * 2]);
        acc.x += u0.x + u1.x + u2.x + u3.x;
        acc.y += u0.y + u1.y + u2.y + u3.y;
    }
    for (; i < len; i++) {
        int s = idx[i];
        float2 u = __half22float2(*(const __half2*)&g_h1h[s * F1 + lane * 2]);
        acc.x += u.x; acc.y += u.y;
    }

    float dv = g_dinv[v];
    float t0 = dv * acc.x + b1[lane * 2];
    float t1 = dv * acc.y + b1[lane * 2 + 1];
    t0 = t0 >= 0.f ? t0 : 0.2f * t0;
    t1 = t1 >= 0.f ? t1 : 0.2f * t1;
    *(float2*)&tw[wid][lane * 2] = make_float2(t0, t1);
    __syncwarp();

    // per-warp W2 apply: lanes 0-15 j in [0,32), lanes 16-31 j in [32,64)
    int m = lane & 15;
    int jb = (lane >> 4) * 32;
    float h = 0.f;
#pragma unroll
    for (int j = 0; j < 32; j++)
        h = fmaf(tw[wid][jb + j], W2s[(jb + j) * F2 + m], h);
    h += __shfl_down_sync(0xffffffffu, h, 16);

    if (lane < 16) g_h2[v * F2 + m] = h * dv;
}

// ---------------------------------------------------------------------------
// Layer-2 aggregation + log_softmax (warp per node).
// Also resets g_hist / g_total for the next graph replay.
// ---------------------------------------------------------------------------
__global__ void gcn_agg2_kernel(const float* __restrict__ b2,
                                float* __restrict__ out) {
    int w = (blockIdx.x * blockDim.x + threadIdx.x) >> 5;
    int lane = threadIdx.x & 31;
    if (w >= NNODES) return;
    int v = w;
    int beg = g_rowptr[v];
    int len = g_hist[v];
    int f = lane & 15;

    float acc = 0.f;
    const int* __restrict__ idx = &g_csr[beg];
    for (int i = (lane >> 4); i < len; i += 2) {
        int s = idx[i];
        acc += g_h2[s * F2 + f];
    }
    acc += __shfl_down_sync(0xffffffffu, acc, 16);

    float dv = g_dinv[v];
    float t = dv * (acc + g_h2[v * F2 + f]) + b2[f];

    float mx = t;
#pragma unroll
    for (int o = 8; o >= 1; o >>= 1)
        mx = fmaxf(mx, __shfl_xor_sync(0xffffffffu, mx, o));
    float ex = expf(t - mx);
    float sum = ex;
#pragma unroll
    for (int o = 8; o >= 1; o >>= 1)
        sum += __shfl_xor_sync(0xffffffffu, sum, o);
    float lse = mx + logf(sum);

    if (lane < 16) out[v * F2 + f] = t - lse;

    // reset CSR state for the next graph replay (deterministic re-entry)
    if (lane == 0) {
        g_hist[v] = 0;
        if (v == 0) g_total = 0;
    }
}

// ---------------------------------------------------------------------------
// Launch: fork-join graph (7 nodes).
//   sA: gemm1_wmma (t=0, NO deps) -> (wait evD) scale_h1 -> evS
//   s0: hist -> scanclaim(evD) -> permute -> (wait evS) agg1gemm2 -> agg2
// ---------------------------------------------------------------------------
extern "C" void kernel_launch(void* const* d_in, const int* in_sizes, int n_in,
                              void* d_out, int out_size) {
    const float* x  = (const float*)d_in[0];
    const int*   ei = (const int*)  d_in[1];
    const float* W1 = (const float*)d_in[2];
    const float* b1 = (const float*)d_in[3];
    const float* W2 = (const float*)d_in[4];
    const float* b2 = (const float*)d_in[5];
    float* out = (float*)d_out;

    const int* src = ei;
    const int* dst = ei + NEDGES;

    const int g1_smem = (BM1 * A_LD + 128 * B_LD) * (int)sizeof(__half); // 35.8KB
    cudaFuncSetAttribute(gcn_gemm1_wmma,
                         cudaFuncAttributeMaxDynamicSharedMemorySize, g1_smem);

    cudaStream_t sA;
    cudaStreamCreateWithFlags(&sA, cudaStreamNonBlocking);
    cudaEvent_t ev0, evD, evS;
    cudaEventCreateWithFlags(&ev0, cudaEventDisableTiming);
    cudaEventCreateWithFlags(&evD, cudaEventDisableTiming);
    cudaEventCreateWithFlags(&evS, cudaEventDisableTiming);

    // fork: side stream joins capture via origin-stream event
    cudaEventRecord(ev0, 0);
    cudaStreamWaitEvent(sA, ev0, 0);

    gcn_gemm1_wmma<<<NP / BM1, 256, g1_smem, sA>>>(x, W1);   // t=0, no deps

    gcn_hist_kernel     <<<(NEDGES / 8 + 255) / 256, 256>>>(dst);   // s0
    gcn_scanclaim_kernel<<<NB1, 256>>>();
    cudaEventRecord(evD, 0);

    cudaStreamWaitEvent(sA, evD, 0);                         // scale needs dinv
    gcn_scale_h1_kernel<<<(NNODES * 16 + 255) / 256, 256, 0, sA>>>();
    cudaEventRecord(evS, sA);

    gcn_permute_kernel<<<(NEDGES / 4 + 255) / 256, 256>>>(src, dst);  // overlaps

    cudaStreamWaitEvent(0, evS, 0);                          // join
    gcn_agg1_gemm2_kernel<<<NNODES / 8, 256>>>(b1, W2);
    gcn_agg2_kernel      <<<(NNODES * 32 + 255) / 256, 256>>>(b2, out);
}